// round 5
// baseline (speedup 1.0000x reference)
#include <cuda_runtime.h>
#include <cuda_bf16.h>

// out[b] = sum_k x[b,k] * |W[k]| * fc1_w[k] + fc1_b
// B=32, K = T*P = 4,000,000
#define NBATCH  32
#define NVEC    1000000            // float4 per batch row
#define GROUPS  37                 // contiguous column chunks
#define CHUNK   27028              // ceil(NVEC / GROUPS)
#define THREADS 256
#define NBLOCKS 592                // 148 SMs * 4 CTAs: one exact wave
#define NUNITS  (NBATCH * GROUPS)  // 1184 = 2 * NBLOCKS

// Zero-at-exit scratch: zero at module load, finalizing block restores zero
// after each run -> deterministic across graph replays. No allocations.
__device__ float    g_partial[NBATCH];
__device__ unsigned g_count;

__global__ __launch_bounds__(THREADS, 4)
void dot_kernel(const float4* __restrict__ x,
                const float4* __restrict__ W,
                const float4* __restrict__ F,
                const float*  __restrict__ fc1_b,
                float* __restrict__ out) {
    const int tid  = threadIdx.x;
    const int lane = tid & 31;
    const int wrp  = tid >> 5;
    __shared__ float sred[THREADS / 32];

#pragma unroll
    for (int pass = 0; pass < 2; pass++) {
        const int u = blockIdx.x + pass * NBLOCKS;   // work unit
        const int b = u & (NBATCH - 1);              // batch (fastest)
        const int g = u >> 5;                        // column chunk
        const int jbeg = g * CHUNK;
        const int jend = min(jbeg + CHUNK, NVEC);

        const float4* __restrict__ xb = x + (size_t)b * NVEC;

        float a0 = 0.f, a1 = 0.f, a2 = 0.f, a3 = 0.f;

#pragma unroll 4
        for (int j = jbeg + tid; j < jend; j += THREADS) {
            // x: read-once 512MB stream -> evict-first, keep W/F in L2
            float4 xv = __ldcs(&xb[j]);
            // W/F: shared by the 32 co-resident batch-blocks -> L2 hits
            float4 w = __ldg(&W[j]);
            float4 f = __ldg(&F[j]);
            a0 = fmaf(xv.x, fabsf(w.x) * f.x, a0);
            a1 = fmaf(xv.y, fabsf(w.y) * f.y, a1);
            a2 = fmaf(xv.z, fabsf(w.z) * f.z, a2);
            a3 = fmaf(xv.w, fabsf(w.w) * f.w, a3);
        }

        float v = (a0 + a1) + (a2 + a3);
#pragma unroll
        for (int off = 16; off; off >>= 1)
            v += __shfl_xor_sync(0xffffffffu, v, off);
        if (lane == 0) sred[wrp] = v;
        __syncthreads();

        if (tid == 0) {
            float s = 0.f;
#pragma unroll
            for (int w2 = 0; w2 < THREADS / 32; w2++) s += sred[w2];
            atomicAdd(&g_partial[b], s);
        }
        __syncthreads();   // protect sred before next pass reuses it
    }

    if (tid == 0) {
        __threadfence();
        unsigned t = atomicAdd(&g_count, 1u);
        if (t == NBLOCKS - 1) {
            __threadfence();
            float bias = fc1_b[0];
#pragma unroll
            for (int i = 0; i < NBATCH; i++) {
                out[i] = g_partial[i] + bias;
                g_partial[i] = 0.0f;
            }
            g_count = 0u;
        }
    }
}

extern "C" void kernel_launch(void* const* d_in, const int* in_sizes, int n_in,
                              void* d_out, int out_size) {
    const float4* x  = (const float4*)d_in[0];  // [32, 4M]
    const float4* W  = (const float4*)d_in[1];  // [4M]
    const float4* F  = (const float4*)d_in[2];  // fc1_w [4M]
    const float*  bb = (const float*)d_in[3];   // fc1_b [1]
    float* out = (float*)d_out;                 // [32]

    (void)in_sizes; (void)n_in; (void)out_size;

    dot_kernel<<<NBLOCKS, THREADS>>>(x, W, F, bb, out);
}

// round 6
// speedup vs baseline: 1.1029x; 1.1029x over previous
#include <cuda_runtime.h>
#include <cuda_bf16.h>

// out[b] = sum_k x[b,k] * |W[k]| * fc1_w[k] + fc1_b
// B=32, K = T*P = 4,000,000 (= 1,000,000 float4 per row)
#define NBATCH   32
#define NVEC     1000000
#define THREADS  256
#define GB       8                  // batches per block
#define BGROUPS  (NBATCH / GB)      // 4
#define CGROUPS  148                // column groups -> grid = 592 = 148*4
#define NBLOCKS  (BGROUPS * CGROUPS)
#define TILE     2048               // float4 per SMEM tile (32 KB)
#define NTILES   ((NVEC + TILE - 1) / TILE)   // 489

__global__ void init_out_kernel(const float* __restrict__ fc1_b,
                                float* __restrict__ out) {
    out[threadIdx.x] = fc1_b[0];
}

__global__ __launch_bounds__(THREADS, 4)
void dot_kernel(const float4* __restrict__ x,
                const float4* __restrict__ W,
                const float4* __restrict__ F,
                float* __restrict__ out) {
    __shared__ float4 c_smem[TILE];          // 32 KB: c = |W|*F tile
    __shared__ float  sred[THREADS / 32][GB];

    const int tid  = threadIdx.x;
    const int lane = tid & 31;
    const int wrp  = tid >> 5;
    const int bg   = blockIdx.x & (BGROUPS - 1);  // batch group 0..3
    const int cg   = blockIdx.x >> 2;             // column group 0..147

    float acc[GB];
#pragma unroll
    for (int b = 0; b < GB; b++) acc[b] = 0.0f;

    // Tile-interleaved sweep: block's consecutive tiles jump CGROUPS*32KB.
    for (int t = cg; t < NTILES; t += CGROUPS) {
        const int t0 = t * TILE;
        const int tl = min(TILE, NVEC - t0);

        // Cooperative load of the coefficient tile (W/F read 4x total
        // chip-wide instead of 32x through L2).
        for (int i = tid; i < tl; i += THREADS) {
            float4 w = __ldg(&W[t0 + i]);
            float4 f = __ldg(&F[t0 + i]);
            c_smem[i] = make_float4(fabsf(w.x) * f.x, fabsf(w.y) * f.y,
                                    fabsf(w.z) * f.z, fabsf(w.w) * f.w);
        }
        __syncthreads();

        // Stream 8 x-rows against the SMEM tile.
#pragma unroll
        for (int bb = 0; bb < GB; bb++) {
            const float4* __restrict__ xb =
                x + (size_t)(bg * GB + bb) * NVEC + t0;
            float s0 = 0.f, s1 = 0.f, s2 = 0.f, s3 = 0.f;
#pragma unroll 4
            for (int i = tid; i < tl; i += THREADS) {
                float4 xv = __ldcs(&xb[i]);   // read-once: evict-first
                float4 c  = c_smem[i];
                s0 = fmaf(xv.x, c.x, s0);
                s1 = fmaf(xv.y, c.y, s1);
                s2 = fmaf(xv.z, c.z, s2);
                s3 = fmaf(xv.w, c.w, s3);
            }
            acc[bb] += (s0 + s1) + (s2 + s3);
        }
        __syncthreads();   // c_smem reused next tile
    }

    // ---- block reduction: warp shfl -> smem -> 8 atomics per block ----
#pragma unroll
    for (int bb = 0; bb < GB; bb++) {
        float v = acc[bb];
#pragma unroll
        for (int off = 16; off; off >>= 1)
            v += __shfl_xor_sync(0xffffffffu, v, off);
        if (lane == 0) sred[wrp][bb] = v;
    }
    __syncthreads();

    if (tid < GB) {
        float s = 0.f;
#pragma unroll
        for (int w2 = 0; w2 < THREADS / 32; w2++) s += sred[w2][tid];
        atomicAdd(&out[bg * GB + tid], s);
    }
}

extern "C" void kernel_launch(void* const* d_in, const int* in_sizes, int n_in,
                              void* d_out, int out_size) {
    const float4* x  = (const float4*)d_in[0];  // [32, 4M]
    const float4* W  = (const float4*)d_in[1];  // [4M]
    const float4* F  = (const float4*)d_in[2];  // fc1_w [4M]
    const float*  bb = (const float*)d_in[3];   // fc1_b [1]
    float* out = (float*)d_out;                 // [32]

    (void)in_sizes; (void)n_in; (void)out_size;

    init_out_kernel<<<1, NBATCH>>>(bb, out);
    dot_kernel<<<NBLOCKS, THREADS>>>(x, W, F, out);
}